// round 8
// baseline (speedup 1.0000x reference)
#include <cuda_runtime.h>
#include <cuda_bf16.h>
#include <cstdint>

#define N0T 4096
#define N1T 8192
#define N2T 4096
#define NTOT 16384
#define CD 64
#define OUTD 32
#define BSEG 64
#define NCTA 148
#define NUNIT 12288
#define NTILE 128

// ---------------- scratch (static device memory; no allocs) ----------------
__device__ float g_dinv[NTOT];
__device__ float g_xA[NTOT * CD];
__device__ float g_xB[NTOT * CD];
__device__ __nv_bfloat16 g_yhi[(size_t)CD * NTOT];
__device__ __nv_bfloat16 g_ylo[(size_t)CD * NTOT];
__device__ float g_part[3 * 8 * BSEG * CD];
__device__ float g_gpart[(size_t)NCTA * 3 * 128 * 64];

// ---------------- helpers ----------------
__device__ __forceinline__ uint32_t smem_u32(const void* p) {
    uint32_t a;
    asm("{ .reg .u64 t; cvta.to.shared.u64 t, %1; cvt.u32.u64 %0, t; }" : "=r"(a) : "l"(p));
    return a;
}
// pack two fp32 into bf16x2 (first arg -> low half)
__device__ __forceinline__ uint32_t pack_bf16x2(float lo, float hi) {
    uint32_t r;
    asm("cvt.rn.bf16x2.f32 %0, %1, %2;" : "=r"(r) : "f"(hi), "f"(lo));
    return r;
}
__device__ __forceinline__ void cp16(uint32_t dst, const void* src) {
    asm volatile("cp.async.cg.shared.global [%0], [%1], 16;" :: "r"(dst), "l"(src));
}
__device__ __forceinline__ void cp_commit() { asm volatile("cp.async.commit_group;" ::: "memory"); }
__device__ __forceinline__ void cp_wait2() { asm volatile("cp.async.wait_group 2;" ::: "memory"); }

__device__ __forceinline__ void mma16816(float* c, const uint32_t* a, uint32_t b0, uint32_t b1) {
    asm volatile(
        "mma.sync.aligned.m16n8k16.row.col.f32.bf16.bf16.f32 "
        "{%0,%1,%2,%3}, {%4,%5,%6,%7}, {%8,%9}, {%0,%1,%2,%3};"
        : "+f"(c[0]), "+f"(c[1]), "+f"(c[2]), "+f"(c[3])
        : "r"(a[0]), "r"(a[1]), "r"(a[2]), "r"(a[3]), "r"(b0), "r"(b1));
}

// unit u -> (tile t, chunk c); tiles: [0,32) rank0 (64 chunks), [32,96) rank1 (128), [96,128) rank2 (64)
__device__ __forceinline__ void decode_unit(int u, int& t, int& c) {
    if (u < 2048) { t = u >> 6; c = u & 63; }
    else if (u < 10240) { int v = u - 2048; t = 32 + (v >> 7); c = v & 127; }
    else { int v = u - 10240; t = 96 + (v >> 6); c = v & 63; }
}
__device__ __forceinline__ void tile_info(int t, int& Nr, int& m0, int& gb, int& ls) {
    if (t < 32) { Nr = N0T; m0 = t << 7; gb = 0; ls = 0; }
    else if (t < 96) { Nr = N1T; m0 = (t - 32) << 7; gb = N0T; ls = 1; }
    else { Nr = N2T; m0 = (t - 96) << 7; gb = N0T + N1T; ls = 2; }
}
__device__ __forceinline__ int cta_of(int u) {
    int bb = (int)(((long long)u * NCTA) / NUNIT);
    while (((bb + 1) * NUNIT) / NCTA <= u) bb++;
    while ((bb * NUNIT) / NCTA > u) bb--;
    return bb;
}

// ==========================================================================
// Kernel 1: rowsums of |L| -> dinv
// ==========================================================================
__global__ void __launch_bounds__(256) rowsum_kernel(const float* __restrict__ L0,
                                                     const float* __restrict__ L1,
                                                     const float* __restrict__ L2) {
    int row = blockIdx.x;
    const float* L;
    int N, lr;
    if (row < N0T) { L = L0; N = N0T; lr = row; }
    else if (row < N0T + N1T) { L = L1; N = N1T; lr = row - N0T; }
    else { L = L2; N = N2T; lr = row - N0T - N1T; }
    const float4* p = (const float4*)(L + (size_t)lr * N);
    int n4 = N >> 2;
    float s = 0.f;
    for (int i = threadIdx.x; i < n4; i += 256) {
        float4 v = __ldcs(p + i);
        s += fabsf(v.x) + fabsf(v.y) + fabsf(v.z) + fabsf(v.w);
    }
    __shared__ float red[8];
    for (int o = 16; o; o >>= 1) s += __shfl_xor_sync(0xFFFFFFFFu, s, o);
    if ((threadIdx.x & 31) == 0) red[threadIdx.x >> 5] = s;
    __syncthreads();
    if (threadIdx.x < 8) {
        float t = red[threadIdx.x];
        for (int o = 4; o; o >>= 1) t += __shfl_xor_sync(0xFFu, t, o);
        if (threadIdx.x == 0) g_dinv[row] = (t != 0.f) ? rsqrtf(t) : 0.f;
    }
}

// ==========================================================================
// Kernel 2: y = (x @ W[layer]) * dinv[row], hi/lo bf16 split, transposed store
// ==========================================================================
__global__ void __launch_bounds__(256) xw_kernel(const float* __restrict__ W0,
                                                 const float* __restrict__ W1,
                                                 const float* __restrict__ W2, int dir) {
    const float* __restrict__ xin = dir ? g_xB : g_xA;
    int row0 = blockIdx.x * 64;
    const float* W;
    if (row0 < N0T) W = W0;
    else if (row0 < N0T + N1T) W = W1;
    else W = W2;

    __shared__ float Ws[64 * 64];
    __shared__ uint32_t tp[64 * 69];
    int tid = threadIdx.x;
    for (int i = tid; i < 4096; i += 256) Ws[i] = W[i];
    __syncthreads();

    int rl = tid >> 2, c0 = (tid & 3) * 16;
    int grow = row0 + rl;
    float xr[64];
    const float4* xp = (const float4*)(xin + (size_t)grow * CD);
#pragma unroll
    for (int i = 0; i < 16; i++) {
        float4 v = __ldg(xp + i);
        xr[4 * i + 0] = v.x; xr[4 * i + 1] = v.y; xr[4 * i + 2] = v.z; xr[4 * i + 3] = v.w;
    }
    float acc[16];
#pragma unroll
    for (int j = 0; j < 16; j++) acc[j] = 0.f;
#pragma unroll
    for (int k = 0; k < 64; k++) {
        float xv = xr[k];
#pragma unroll
        for (int j = 0; j < 16; j++) acc[j] += xv * Ws[k * 64 + c0 + j];
    }
    float dv = g_dinv[grow];
#pragma unroll
    for (int j = 0; j < 16; j++) {
        float v = acc[j] * dv;
        uint32_t h = (uint32_t)__bfloat16_as_ushort(__float2bfloat16(v));
        float fh = __uint_as_float(h << 16);
        uint32_t l = (uint32_t)__bfloat16_as_ushort(__float2bfloat16(v - fh));
        tp[(c0 + j) * 69 + rl] = h | (l << 16);
    }
    __syncthreads();

    int ch = tid >> 2, seg = tid & 3;
    uint32_t hh[8], ll[8];
#pragma unroll
    for (int i = 0; i < 8; i++) {
        uint32_t p0 = tp[ch * 69 + seg * 16 + 2 * i];
        uint32_t p1 = tp[ch * 69 + seg * 16 + 2 * i + 1];
        hh[i] = (p0 & 0xFFFFu) | (p1 << 16);
        ll[i] = (p0 >> 16) | (p1 & 0xFFFF0000u);
    }
    size_t ob = (size_t)ch * NTOT + row0 + seg * 16;
    *(uint4*)(&g_yhi[ob]) = make_uint4(hh[0], hh[1], hh[2], hh[3]);
    *(uint4*)(&g_yhi[ob + 8]) = make_uint4(hh[4], hh[5], hh[6], hh[7]);
    *(uint4*)(&g_ylo[ob]) = make_uint4(ll[0], ll[1], ll[2], ll[3]);
    *(uint4*)(&g_ylo[ob + 8]) = make_uint4(ll[4], ll[5], ll[6], ll[7]);
}

// ==========================================================================
// Kernel 3: balanced big GEMM via mma.sync bf16 hi/lo (3 MMAs / k16-tile)
// 148 CTAs x 256 thr, equal (tile,chunk)-unit split, partials to scratch.
// A: global->regs in fragment layout. B: cp.async 4-stage smem pipeline.
// ==========================================================================
#define STG_BYTES 18432
#define SMEMSZ (4 * STG_BYTES)

__global__ void __launch_bounds__(256, 1) spmm_kernel(const float* __restrict__ L0,
                                                      const float* __restrict__ L1,
                                                      const float* __restrict__ L2) {
    extern __shared__ char smem[];
    const uint32_t sbase = smem_u32(smem);
    const int tid = threadIdx.x;
    const int lane = tid & 31, w = tid >> 5;
    const int b = blockIdx.x;
    const int u0 = (b * NUNIT) / NCTA;
    const int u1 = ((b + 1) * NUNIT) / NCTA;
    const int nun = u1 - u0;

    auto Lsel = [&](int ls) { return ls == 0 ? L0 : (ls == 1 ? L1 : L2); };

    // issue one 64-k B chunk (hi+lo, 16 KB) into stage s
    auto issueB = [&](int u, int s) {
        int t, c; decode_unit(u, t, c);
        int Nr, m0, gb, ls; tile_info(t, Nr, m0, gb, ls);
        int n = tid >> 2, seg = tid & 3;
        size_t src = (size_t)n * NTOT + gb + c * 64 + seg * 16;
        uint32_t dst = sbase + s * STG_BYTES + n * 144 + seg * 32;
        cp16(dst, g_yhi + src);
        cp16(dst + 16, g_yhi + src + 8);
        cp16(dst + 9216, g_ylo + src);
        cp16(dst + 9216 + 16, g_ylo + src + 8);
    };

    // load A fragments (raw fp32) for one chunk into regs
    auto loadA = [&](int u, float2* dst) {
        int t, c; decode_unit(u, t, c);
        int Nr, m0, gb, ls; tile_info(t, Nr, m0, gb, ls);
        const float* L = Lsel(ls);
        int r0 = m0 + 16 * w + (lane >> 2);
        const float* p0 = L + (size_t)r0 * Nr + c * 64 + (lane & 3) * 2;
        const float* p1 = p0 + (size_t)8 * Nr;
#pragma unroll
        for (int kt = 0; kt < 4; kt++) {
            dst[kt * 4 + 0] = __ldcs((const float2*)(p0 + kt * 16));
            dst[kt * 4 + 1] = __ldcs((const float2*)(p1 + kt * 16));
            dst[kt * 4 + 2] = __ldcs((const float2*)(p0 + kt * 16 + 8));
            dst[kt * 4 + 3] = __ldcs((const float2*)(p1 + kt * 16 + 8));
        }
    };

    // prologue: 3 stages in flight
    for (int p = 0; p < 3; p++) {
        if (p < nun) issueB(u0 + p, p);
        cp_commit();
    }

    float2 cur[16], nxt[16];
    loadA(u0, cur);

    float acc[8][4];
#pragma unroll
    for (int nt = 0; nt < 8; nt++)
#pragma unroll
        for (int q = 0; q < 4; q++) acc[nt][q] = 0.f;

    int curtile, cc0;
    decode_unit(u0, curtile, cc0);
    int j = 0;

    const int fragoff = (lane >> 2) * 144 + (lane & 3) * 4;

    for (int i = 0; i < nun; i++) {
        cp_wait2();
        __syncthreads();
        if (i + 3 < nun) issueB(u0 + i + 3, (i + 3) & 3);
        cp_commit();
        if (i + 1 < nun) loadA(u0 + i + 1, nxt);

        const char* stg = smem + (i & 3) * STG_BYTES;
#pragma unroll
        for (int kt = 0; kt < 4; kt++) {
            uint32_t ahi[4], alo[4];
#pragma unroll
            for (int q = 0; q < 4; q++) {
                float2 f = cur[kt * 4 + q];
                uint32_t h = pack_bf16x2(f.x, f.y);
                float rx = f.x - __uint_as_float(h << 16);
                float ry = f.y - __uint_as_float(h & 0xFFFF0000u);
                ahi[q] = h;
                alo[q] = pack_bf16x2(rx, ry);
            }
#pragma unroll
            for (int nt = 0; nt < 8; nt++) {
                const char* p = stg + nt * 8 * 144 + kt * 32 + fragoff;
                uint32_t b0h = *(const uint32_t*)(p);
                uint32_t b1h = *(const uint32_t*)(p + 16);
                uint32_t b0l = *(const uint32_t*)(p + 9216);
                uint32_t b1l = *(const uint32_t*)(p + 9216 + 16);
                mma16816(acc[nt], ahi, b0h, b1h);
                mma16816(acc[nt], ahi, b0l, b1l);
                mma16816(acc[nt], alo, b0h, b1h);
            }
        }

        int ntile = -1;
        if (i + 1 < nun) { int cc; decode_unit(u0 + i + 1, ntile, cc); }
        if (ntile != curtile) {
            float* pp = g_gpart + ((size_t)(b * 3 + j) << 13);
            int r0 = 16 * w + (lane >> 2);
            int cb = (lane & 3) * 2;
#pragma unroll
            for (int nt = 0; nt < 8; nt++) {
                int col = nt * 8 + cb;
                *(float2*)(pp + r0 * 64 + col) = make_float2(acc[nt][0], acc[nt][1]);
                *(float2*)(pp + (r0 + 8) * 64 + col) = make_float2(acc[nt][2], acc[nt][3]);
#pragma unroll
                for (int q = 0; q < 4; q++) acc[nt][q] = 0.f;
            }
            j++;
            curtile = ntile;
        }
#pragma unroll
        for (int q = 0; q < 16; q++) cur[q] = nxt[q];
    }
}

// ==========================================================================
// Kernel 3b: combine partials per tile, apply dinv_i + relu
// ==========================================================================
__global__ void __launch_bounds__(256) combine_kernel(int dir) {
    float* __restrict__ xout = dir ? g_xA : g_xB;
    int t = blockIdx.x;
    int Nr, m0, gb, ls;
    tile_info(t, Nr, m0, gb, ls);
    int tu0, tlen;
    if (t < 32) { tu0 = t * 64; tlen = 64; }
    else if (t < 96) { tu0 = 2048 + (t - 32) * 128; tlen = 128; }
    else { tu0 = 10240 + (t - 96) * 64; tlen = 64; }
    int blo = cta_of(tu0), bhi = cta_of(tu0 + tlen - 1);

    int row = threadIdx.x >> 1, cb = (threadIdx.x & 1) * 32;
    float4 a[8];
#pragma unroll
    for (int q = 0; q < 8; q++) a[q] = make_float4(0.f, 0.f, 0.f, 0.f);
    for (int bb = blo; bb <= bhi; bb++) {
        int us = (bb * NUNIT) / NCTA;
        int ft, fc;
        decode_unit(us, ft, fc);
        const float4* p = (const float4*)(g_gpart + ((size_t)(bb * 3 + (t - ft)) << 13) +
                                          row * 64 + cb);
#pragma unroll
        for (int q = 0; q < 8; q++) {
            float4 v = p[q];
            a[q].x += v.x; a[q].y += v.y; a[q].z += v.z; a[q].w += v.w;
        }
    }
    float dv = g_dinv[gb + m0 + row];
    float4* o = (float4*)(xout + (size_t)(gb + m0 + row) * CD + cb);
#pragma unroll
    for (int q = 0; q < 8; q++)
        o[q] = make_float4(fmaxf(dv * a[q].x, 0.f), fmaxf(dv * a[q].y, 0.f),
                           fmaxf(dv * a[q].z, 0.f), fmaxf(dv * a[q].w, 0.f));
}

// ==========================================================================
// Kernel 4: deterministic segment pooling (partials per row-chunk)
// ==========================================================================
__global__ void __launch_bounds__(64) pool_kernel(const int* __restrict__ bel0,
                                                  const int* __restrict__ bel1,
                                                  const int* __restrict__ bel2) {
    int x = blockIdx.x;
    int r = x >> 9;
    int rem = x & 511;
    int k = rem >> 6;
    int b = rem & 63;
    const int* bel;
    int Nr, gb;
    if (r == 0)      { bel = bel0; Nr = N0T; gb = 0; }
    else if (r == 1) { bel = bel1; Nr = N1T; gb = N0T; }
    else             { bel = bel2; Nr = N2T; gb = N0T + N1T; }
    int chunk = Nr >> 3;
    int i0 = k * chunk;
    int t = threadIdx.x;
    const float* xp = g_xA + (size_t)(gb + i0) * CD + t;
    const int* bp = bel + i0;
    float acc = 0.f;
#pragma unroll 4
    for (int i = 0; i < chunk; i++) {
        if (__ldg(bp + i) == b) acc += __ldg(xp + (size_t)i * CD);
    }
    g_part[((r * 8 + k) * BSEG + b) * CD + t] = acc;
}

// ==========================================================================
// Kernel 5: readout
// ==========================================================================
__global__ void __launch_bounds__(256) readout_kernel(const float* __restrict__ Wr0,
                                                      const float* __restrict__ br0,
                                                      const float* __restrict__ Wr1,
                                                      const float* __restrict__ br1,
                                                      const float* __restrict__ Wr2,
                                                      const float* __restrict__ br2,
                                                      float* __restrict__ out) {
    __shared__ float ps[3 * 8 * 64];
    int tid = threadIdx.x;
    int b0 = blockIdx.x * 8;
    for (int i = tid; i < 1536; i += 256) {
        int r = i / 512;
        int rem = i % 512;
        int bl = rem / 64;
        int c = rem % 64;
        float s = 0.f;
#pragma unroll
        for (int k = 0; k < 8; k++)
            s += g_part[((r * 8 + k) * BSEG + (b0 + bl)) * CD + c];
        ps[i] = s;
    }
    __syncthreads();
    int bl = tid >> 5, o = tid & 31;
    float acc = __ldg(br0 + o) + __ldg(br1 + o) + __ldg(br2 + o);
    const float* Wr[3] = {Wr0, Wr1, Wr2};
#pragma unroll
    for (int r = 0; r < 3; r++) {
        const float* w = Wr[r];
        const float* p = &ps[r * 512 + bl * 64];
#pragma unroll 8
        for (int c = 0; c < 64; c++) acc += p[c] * __ldg(w + c * OUTD + o);
    }
    out[(b0 + bl) * OUTD + o] = acc;
}

// ==========================================================================
// host
// ==========================================================================
extern "C" void kernel_launch(void* const* d_in, const int* in_sizes, int n_in,
                              void* d_out, int out_size) {
    const float* x0 = (const float*)d_in[0];
    const float* x1 = (const float*)d_in[1];
    const float* x2 = (const float*)d_in[2];
    const float* L0 = (const float*)d_in[3];
    const float* L1 = (const float*)d_in[4];
    const float* L2 = (const float*)d_in[5];
    const int* bel0 = (const int*)d_in[6];
    const int* bel1 = (const int*)d_in[7];
    const int* bel2 = (const int*)d_in[8];
    const float* W0 = (const float*)d_in[9];
    const float* W1 = (const float*)d_in[10];
    const float* W2 = (const float*)d_in[11];
    const float* Wr0 = (const float*)d_in[12];
    const float* br0 = (const float*)d_in[13];
    const float* Wr1 = (const float*)d_in[14];
    const float* br1 = (const float*)d_in[15];
    const float* Wr2 = (const float*)d_in[16];
    const float* br2 = (const float*)d_in[17];

    cudaFuncSetAttribute(spmm_kernel, cudaFuncAttributeMaxDynamicSharedMemorySize, SMEMSZ);

    cudaMemcpyToSymbolAsync(g_xA, x0, (size_t)N0T * CD * 4, 0, cudaMemcpyDeviceToDevice, 0);
    cudaMemcpyToSymbolAsync(g_xA, x1, (size_t)N1T * CD * 4, (size_t)N0T * CD * 4,
                            cudaMemcpyDeviceToDevice, 0);
    cudaMemcpyToSymbolAsync(g_xA, x2, (size_t)N2T * CD * 4, (size_t)(N0T + N1T) * CD * 4,
                            cudaMemcpyDeviceToDevice, 0);

    rowsum_kernel<<<NTOT, 256>>>(L0, L1, L2);

    for (int layer = 0; layer < 2; layer++) {
        xw_kernel<<<NTOT / 64, 256>>>(W0 + layer * CD * CD, W1 + layer * CD * CD,
                                      W2 + layer * CD * CD, layer);
        spmm_kernel<<<NCTA, 256, SMEMSZ>>>(L0, L1, L2);
        combine_kernel<<<NTILE, 256>>>(layer);
    }

    pool_kernel<<<3 * 8 * BSEG, 64>>>(bel0, bel1, bel2);
    readout_kernel<<<8, 256>>>(Wr0, br0, Wr1, br1, Wr2, br2, (float*)d_out);
}

// round 10
// speedup vs baseline: 1.5764x; 1.5764x over previous
#include <cuda_runtime.h>
#include <cuda_fp16.h>
#include <cstdint>

#define N0T 4096
#define N1T 8192
#define N2T 4096
#define NTOT 16384
#define CD 64
#define OUTD 32
#define BSEG 64
#define NCTA 296
#define NUNIT 12288
#define NTILE 128

// ---------------- scratch (static device memory; no allocs) ----------------
__device__ float g_dinv[NTOT];
__device__ float g_xB[NTOT * CD];   // layer0 output
__device__ float g_xA[NTOT * CD];   // layer1 output (pool input)
__device__ __half g_yh[(size_t)CD * NTOT];
__device__ float g_part[64 * BSEG * CD];
__device__ float g_gpart[(size_t)NCTA * 3 * 128 * 64];

// ---------------- helpers ----------------
__device__ __forceinline__ uint32_t smem_u32(const void* p) {
    uint32_t a;
    asm("{ .reg .u64 t; cvta.to.shared.u64 t, %1; cvt.u32.u64 %0, t; }" : "=r"(a) : "l"(p));
    return a;
}
__device__ __forceinline__ uint32_t pack_f16x2(float lo, float hi) {
    __half2 h = __floats2half2_rn(lo, hi);  // lo -> low half
    return *reinterpret_cast<uint32_t*>(&h);
}
__device__ __forceinline__ void cp16(uint32_t dst, const void* src) {
    asm volatile("cp.async.cg.shared.global [%0], [%1], 16;" :: "r"(dst), "l"(src));
}
__device__ __forceinline__ void cp_commit() { asm volatile("cp.async.commit_group;" ::: "memory"); }
__device__ __forceinline__ void cp_wait2() { asm volatile("cp.async.wait_group 2;" ::: "memory"); }

__device__ __forceinline__ void mma16816f(float* c, const uint32_t* a, uint32_t b0, uint32_t b1) {
    asm volatile(
        "mma.sync.aligned.m16n8k16.row.col.f32.f16.f16.f32 "
        "{%0,%1,%2,%3}, {%4,%5,%6,%7}, {%8,%9}, {%0,%1,%2,%3};"
        : "+f"(c[0]), "+f"(c[1]), "+f"(c[2]), "+f"(c[3])
        : "r"(a[0]), "r"(a[1]), "r"(a[2]), "r"(a[3]), "r"(b0), "r"(b1));
}

// unit u -> (tile t, chunk c); tiles: [0,32) rank0 (64 chunks), [32,96) rank1 (128), [96,128) rank2 (64)
__device__ __forceinline__ void decode_unit(int u, int& t, int& c) {
    if (u < 2048) { t = u >> 6; c = u & 63; }
    else if (u < 10240) { int v = u - 2048; t = 32 + (v >> 7); c = v & 127; }
    else { int v = u - 10240; t = 96 + (v >> 6); c = v & 63; }
}
__device__ __forceinline__ void tile_info(int t, int& Nr, int& m0, int& gb, int& ls) {
    if (t < 32) { Nr = N0T; m0 = t << 7; gb = 0; ls = 0; }
    else if (t < 96) { Nr = N1T; m0 = (t - 32) << 7; gb = N0T; ls = 1; }
    else { Nr = N2T; m0 = (t - 96) << 7; gb = N0T + N1T; ls = 2; }
}
__device__ __forceinline__ int cta_of(int u) {
    int bb = (int)(((long long)u * NCTA) / NUNIT);
    while (((bb + 1) * NUNIT) / NCTA <= u) bb++;
    while ((bb * NUNIT) / NCTA > u) bb--;
    return bb;
}

// ==========================================================================
// Kernel 1: rowsums of |L| -> dinv
// ==========================================================================
__global__ void __launch_bounds__(256) rowsum_kernel(const float* __restrict__ L0,
                                                     const float* __restrict__ L1,
                                                     const float* __restrict__ L2) {
    int row = blockIdx.x;
    const float* L;
    int N, lr;
    if (row < N0T) { L = L0; N = N0T; lr = row; }
    else if (row < N0T + N1T) { L = L1; N = N1T; lr = row - N0T; }
    else { L = L2; N = N2T; lr = row - N0T - N1T; }
    const float4* p = (const float4*)(L + (size_t)lr * N);
    int n4 = N >> 2;
    float s = 0.f;
    for (int i = threadIdx.x; i < n4; i += 256) {
        float4 v = __ldcs(p + i);
        s += fabsf(v.x) + fabsf(v.y) + fabsf(v.z) + fabsf(v.w);
    }
    __shared__ float red[8];
    for (int o = 16; o; o >>= 1) s += __shfl_xor_sync(0xFFFFFFFFu, s, o);
    if ((threadIdx.x & 31) == 0) red[threadIdx.x >> 5] = s;
    __syncthreads();
    if (threadIdx.x < 8) {
        float t = red[threadIdx.x];
        for (int o = 4; o; o >>= 1) t += __shfl_xor_sync(0xFFu, t, o);
        if (threadIdx.x == 0) g_dinv[row] = (t != 0.f) ? rsqrtf(t) : 0.f;
    }
}

// ==========================================================================
// Kernel 2: y = (x @ W[layer]) * dinv[row] -> fp16, transposed store yT[c][row]
// layer 0 reads raw inputs; layer 1 reads g_xB
// ==========================================================================
__global__ void __launch_bounds__(256) xw_kernel(const float* __restrict__ W0,
                                                 const float* __restrict__ W1,
                                                 const float* __restrict__ W2,
                                                 const float* __restrict__ x0,
                                                 const float* __restrict__ x1,
                                                 const float* __restrict__ x2, int layer) {
    int row0 = blockIdx.x * 64;
    const float* W;
    const float* xsrc;
    int lrow0;
    if (row0 < N0T) { W = W0; xsrc = x0; lrow0 = row0; }
    else if (row0 < N0T + N1T) { W = W1; xsrc = x1; lrow0 = row0 - N0T; }
    else { W = W2; xsrc = x2; lrow0 = row0 - N0T - N1T; }
    if (layer) { xsrc = g_xB; lrow0 = row0; }

    __shared__ float Ws[64 * 64];
    __shared__ uint32_t tp[64 * 69];
    int tid = threadIdx.x;
    for (int i = tid; i < 4096; i += 256) Ws[i] = W[i];
    __syncthreads();

    int rl = tid >> 2, c0 = (tid & 3) * 16;
    int grow = row0 + rl;
    float xr[64];
    const float4* xp = (const float4*)(xsrc + (size_t)(lrow0 + rl) * CD);
#pragma unroll
    for (int i = 0; i < 16; i++) {
        float4 v = __ldg(xp + i);
        xr[4 * i + 0] = v.x; xr[4 * i + 1] = v.y; xr[4 * i + 2] = v.z; xr[4 * i + 3] = v.w;
    }
    float acc[16];
#pragma unroll
    for (int j = 0; j < 16; j++) acc[j] = 0.f;
#pragma unroll
    for (int k = 0; k < 64; k++) {
        float xv = xr[k];
#pragma unroll
        for (int j = 0; j < 16; j++) acc[j] += xv * Ws[k * 64 + c0 + j];
    }
    float dv = g_dinv[grow];
#pragma unroll
    for (int j = 0; j < 16; j++) {
        float v = acc[j] * dv;
        tp[(c0 + j) * 69 + rl] = (uint32_t)__half_as_ushort(__float2half_rn(v));
    }
    __syncthreads();

    int ch = tid >> 2, seg = tid & 3;  // 16 rows per thread
    uint32_t hh[8];
#pragma unroll
    for (int i = 0; i < 8; i++) {
        uint32_t p0 = tp[ch * 69 + seg * 16 + 2 * i];
        uint32_t p1 = tp[ch * 69 + seg * 16 + 2 * i + 1];
        hh[i] = (p0 & 0xFFFFu) | (p1 << 16);
    }
    size_t ob = (size_t)ch * NTOT + row0 + seg * 16;
    *(uint4*)(&g_yh[ob]) = make_uint4(hh[0], hh[1], hh[2], hh[3]);
    *(uint4*)(&g_yh[ob + 8]) = make_uint4(hh[4], hh[5], hh[6], hh[7]);
}

// ==========================================================================
// Kernel 3: balanced big GEMM via mma.sync fp16 (1 MMA / k16-tile)
// 296 CTAs x 256 thr (2 CTAs/SM), equal (tile,chunk)-unit split, partials out.
// A: global->regs->f16 in fragment layout. B: cp.async 4-stage smem pipeline.
// ==========================================================================
#define STG_BYTES 9216
#define SMEMSZ (4 * STG_BYTES)

__global__ void __launch_bounds__(256, 2) spmm_kernel(const float* __restrict__ L0,
                                                      const float* __restrict__ L1,
                                                      const float* __restrict__ L2) {
    extern __shared__ char smem[];
    const uint32_t sbase = smem_u32(smem);
    const int tid = threadIdx.x;
    const int lane = tid & 31, w = tid >> 5;
    const int b = blockIdx.x;
    const int u0 = (b * NUNIT) / NCTA;
    const int u1 = ((b + 1) * NUNIT) / NCTA;
    const int nun = u1 - u0;

    auto Lsel = [&](int ls) { return ls == 0 ? L0 : (ls == 1 ? L1 : L2); };

    // issue one 64-k B chunk (8 KB fp16) into stage s
    auto issueB = [&](int u, int s) {
        int t, c; decode_unit(u, t, c);
        int Nr, m0, gb, ls; tile_info(t, Nr, m0, gb, ls);
        int n = tid >> 2, seg = tid & 3;
        size_t src = (size_t)n * NTOT + gb + c * 64 + seg * 16;
        uint32_t dst = sbase + s * STG_BYTES + n * 144 + seg * 32;
        cp16(dst, g_yh + src);
        cp16(dst + 16, g_yh + src + 8);
    };

    // load A fragments (raw fp32) for one chunk into regs
    auto loadA = [&](int u, float2* dst) {
        int t, c; decode_unit(u, t, c);
        int Nr, m0, gb, ls; tile_info(t, Nr, m0, gb, ls);
        const float* L = Lsel(ls);
        int r0 = m0 + 16 * w + (lane >> 2);
        const float* p0 = L + (size_t)r0 * Nr + c * 64 + (lane & 3) * 2;
        const float* p1 = p0 + (size_t)8 * Nr;
#pragma unroll
        for (int kt = 0; kt < 4; kt++) {
            dst[kt * 4 + 0] = __ldcs((const float2*)(p0 + kt * 16));
            dst[kt * 4 + 1] = __ldcs((const float2*)(p1 + kt * 16));
            dst[kt * 4 + 2] = __ldcs((const float2*)(p0 + kt * 16 + 8));
            dst[kt * 4 + 3] = __ldcs((const float2*)(p1 + kt * 16 + 8));
        }
    };

    // prologue: 3 stages in flight
    for (int p = 0; p < 3; p++) {
        if (p < nun) issueB(u0 + p, p);
        cp_commit();
    }

    float2 raw[16];
    loadA(u0, raw);
    uint32_t cur[16];
#pragma unroll
    for (int q = 0; q < 16; q++) cur[q] = pack_f16x2(raw[q].x, raw[q].y);

    float acc[8][4];
#pragma unroll
    for (int nt = 0; nt < 8; nt++)
#pragma unroll
        for (int q = 0; q < 4; q++) acc[nt][q] = 0.f;

    int curtile, cc0;
    decode_unit(u0, curtile, cc0);
    int j = 0;

    const int fragoff = (lane >> 2) * 144 + (lane & 3) * 4;

    for (int i = 0; i < nun; i++) {
        cp_wait2();
        __syncthreads();
        if (i + 3 < nun) issueB(u0 + i + 3, (i + 3) & 3);
        cp_commit();
        if (i + 1 < nun) loadA(u0 + i + 1, raw);

        const char* stg = smem + (i & 3) * STG_BYTES;
#pragma unroll
        for (int kt = 0; kt < 4; kt++) {
            const uint32_t* a = &cur[kt * 4];
#pragma unroll
            for (int nt = 0; nt < 8; nt++) {
                const char* p = stg + nt * 8 * 144 + kt * 32 + fragoff;
                uint32_t b0 = *(const uint32_t*)(p);
                uint32_t b1 = *(const uint32_t*)(p + 16);
                mma16816f(acc[nt], a, b0, b1);
            }
        }

        int ntile = -1;
        if (i + 1 < nun) { int cc; decode_unit(u0 + i + 1, ntile, cc); }
        if (ntile != curtile) {
            float* pp = g_gpart + ((size_t)(b * 3 + j) << 13);
            int r0 = 16 * w + (lane >> 2);
            int cb = (lane & 3) * 2;
#pragma unroll
            for (int nt = 0; nt < 8; nt++) {
                int col = nt * 8 + cb;
                *(float2*)(pp + r0 * 64 + col) = make_float2(acc[nt][0], acc[nt][1]);
                *(float2*)(pp + (r0 + 8) * 64 + col) = make_float2(acc[nt][2], acc[nt][3]);
#pragma unroll
                for (int q = 0; q < 4; q++) acc[nt][q] = 0.f;
            }
            j++;
            curtile = ntile;
        }
#pragma unroll
        for (int q = 0; q < 16; q++) cur[q] = pack_f16x2(raw[q].x, raw[q].y);
    }
}

// ==========================================================================
// Kernel 3b: combine partials per tile, apply dinv_i + relu
// ==========================================================================
__global__ void __launch_bounds__(256) combine_kernel(int dir) {
    float* __restrict__ xout = dir ? g_xA : g_xB;
    int t = blockIdx.x;
    int Nr, m0, gb, ls;
    tile_info(t, Nr, m0, gb, ls);
    int tu0, tlen;
    if (t < 32) { tu0 = t * 64; tlen = 64; }
    else if (t < 96) { tu0 = 2048 + (t - 32) * 128; tlen = 128; }
    else { tu0 = 10240 + (t - 96) * 64; tlen = 64; }
    int blo = cta_of(tu0), bhi = cta_of(tu0 + tlen - 1);

    int row = threadIdx.x >> 1, cb = (threadIdx.x & 1) * 32;
    float4 a[8];
#pragma unroll
    for (int q = 0; q < 8; q++) a[q] = make_float4(0.f, 0.f, 0.f, 0.f);
    for (int bb = blo; bb <= bhi; bb++) {
        int us = (bb * NUNIT) / NCTA;
        int ft, fc;
        decode_unit(us, ft, fc);
        const float4* p = (const float4*)(g_gpart + ((size_t)(bb * 3 + (t - ft)) << 13) +
                                          row * 64 + cb);
#pragma unroll
        for (int q = 0; q < 8; q++) {
            float4 v = p[q];
            a[q].x += v.x; a[q].y += v.y; a[q].z += v.z; a[q].w += v.w;
        }
    }
    float dv = g_dinv[gb + m0 + row];
    float4* o = (float4*)(xout + (size_t)(gb + m0 + row) * CD + cb);
#pragma unroll
    for (int q = 0; q < 8; q++)
        o[q] = make_float4(fmaxf(dv * a[q].x, 0.f), fmaxf(dv * a[q].y, 0.f),
                           fmaxf(dv * a[q].z, 0.f), fmaxf(dv * a[q].w, 0.f));
}

// ==========================================================================
// Kernel 4: deterministic segment pooling — reads x exactly once.
// 64 blocks (16 rank0, 32 rank1, 16 rank2) x 64 threads; smem bins, no atomics.
// ==========================================================================
__global__ void __launch_bounds__(64) pool_kernel(const int* __restrict__ bel0,
                                                  const int* __restrict__ bel1,
                                                  const int* __restrict__ bel2) {
    int blk = blockIdx.x;
    const int* bel;
    int gb, lrow0;
    if (blk < 16) { bel = bel0; gb = 0; lrow0 = blk * 256; }
    else if (blk < 48) { bel = bel1; gb = N0T; lrow0 = (blk - 16) * 256; }
    else { bel = bel2; gb = N0T + N1T; lrow0 = (blk - 48) * 256; }
    int t = threadIdx.x;

    __shared__ float bins[BSEG * CD];
    for (int i = t; i < BSEG * CD; i += 64) bins[i] = 0.f;
    __syncthreads();

    const float* xp = g_xA + (size_t)(gb + lrow0) * CD + t;
    const int* bp = bel + lrow0;
#pragma unroll 4
    for (int i = 0; i < 256; i++) {
        int bseg = __ldg(bp + i);
        float v = __ldg(xp + (size_t)i * CD);
        bins[bseg * CD + t] += v;
    }
    __syncthreads();
    for (int i = t; i < BSEG * CD; i += 64) g_part[blk * (BSEG * CD) + i] = bins[i];
}

// ==========================================================================
// Kernel 5: readout  out[b][o] = sum_r pooled_r @ Wr_r + br_r
// ==========================================================================
__global__ void __launch_bounds__(256) readout_kernel(const float* __restrict__ Wr0,
                                                      const float* __restrict__ br0,
                                                      const float* __restrict__ Wr1,
                                                      const float* __restrict__ br1,
                                                      const float* __restrict__ Wr2,
                                                      const float* __restrict__ br2,
                                                      float* __restrict__ out) {
    __shared__ float ps[3 * 8 * 64];  // [r][b_local][c]
    int tid = threadIdx.x;
    int b0 = blockIdx.x * 8;
    for (int i = tid; i < 1536; i += 256) {
        int r = i / 512;
        int rem = i % 512;
        int bl = rem / 64;
        int c = rem % 64;
        int kb = (r == 0) ? 0 : (r == 1 ? 16 : 48);
        int kn = (r == 1) ? 32 : 16;
        float s = 0.f;
        for (int k = 0; k < kn; k++)
            s += g_part[(kb + k) * (BSEG * CD) + (b0 + bl) * 64 + c];
        ps[i] = s;
    }
    __syncthreads();
    int bl = tid >> 5, o = tid & 31;
    float acc = __ldg(br0 + o) + __ldg(br1 + o) + __ldg(br2 + o);
    const float* Wr[3] = {Wr0, Wr1, Wr2};
#pragma unroll
    for (int r = 0; r < 3; r++) {
        const float* w = Wr[r];
        const float* p = &ps[r * 512 + bl * 64];
#pragma unroll 8
        for (int c = 0; c < 64; c++) acc += p[c] * __ldg(w + c * OUTD + o);
    }
    out[(b0 + bl) * OUTD + o] = acc;
}

// ==========================================================================
// host
// ==========================================================================
extern "C" void kernel_launch(void* const* d_in, const int* in_sizes, int n_in,
                              void* d_out, int out_size) {
    const float* x0 = (const float*)d_in[0];
    const float* x1 = (const float*)d_in[1];
    const float* x2 = (const float*)d_in[2];
    const float* L0 = (const float*)d_in[3];
    const float* L1 = (const float*)d_in[4];
    const float* L2 = (const float*)d_in[5];
    const int* bel0 = (const int*)d_in[6];
    const int* bel1 = (const int*)d_in[7];
    const int* bel2 = (const int*)d_in[8];
    const float* W0 = (const float*)d_in[9];
    const float* W1 = (const float*)d_in[10];
    const float* W2 = (const float*)d_in[11];
    const float* Wr0 = (const float*)d_in[12];
    const float* br0 = (const float*)d_in[13];
    const float* Wr1 = (const float*)d_in[14];
    const float* br1 = (const float*)d_in[15];
    const float* Wr2 = (const float*)d_in[16];
    const float* br2 = (const float*)d_in[17];

    cudaFuncSetAttribute(spmm_kernel, cudaFuncAttributeMaxDynamicSharedMemorySize, SMEMSZ);

    rowsum_kernel<<<NTOT, 256>>>(L0, L1, L2);

    for (int layer = 0; layer < 2; layer++) {
        xw_kernel<<<NTOT / 64, 256>>>(W0 + layer * CD * CD, W1 + layer * CD * CD,
                                      W2 + layer * CD * CD, x0, x1, x2, layer);
        spmm_kernel<<<NCTA, 256, SMEMSZ>>>(L0, L1, L2);
        combine_kernel<<<NTILE, 256>>>(layer);
    }

    pool_kernel<<<64, 64>>>(bel0, bel1, bel2);
    readout_kernel<<<8, 256>>>(Wr0, br0, Wr1, br1, Wr2, br2, (float*)d_out);
}